// round 1
// baseline (speedup 1.0000x reference)
#include <cuda_runtime.h>
#include <math.h>

// Problem constants
#define CDIM 1024           // N_EMBED
#define NHEADS 16
#define HDIM 64             // head size
#define SEQ 2048
#define BATCH 2
#define BT (BATCH * SEQ)    // 4096 rows in the GEMMs
#define QTILES (SEQ / 64)   // 32

// ---------------------------------------------------------------------------
// Scratch (no cudaMalloc allowed): Q/K/V in [B*H, T, D] layout, att out [B,T,C]
// ---------------------------------------------------------------------------
__device__ float g_q[BATCH * NHEADS * SEQ * HDIM];
__device__ float g_k[BATCH * NHEADS * SEQ * HDIM];
__device__ float g_v[BATCH * NHEADS * SEQ * HDIM];
__device__ float g_att[BT * CDIM];

// ---------------------------------------------------------------------------
// Tiled fp32 GEMM body: C[128x128] tile, K=1024, lda=ldb=1024.
// 256 threads, 8x8 micro-tile per thread, BK=16.
// As stored transposed [k][m] with stride 132 (conflict-free frag reads).
// ---------------------------------------------------------------------------
#define BK 16
#define AS_STRIDE 132

__device__ __forceinline__ void gemm_body(const float* __restrict__ A,
                                          const float* __restrict__ B,
                                          int m0, int n0, float (&acc)[8][8]) {
    __shared__ float As[BK * AS_STRIDE];
    __shared__ float Bs[BK * 128];
    const int tid = threadIdx.x;
    const int tx = tid & 15;
    const int ty = tid >> 4;

    for (int k0 = 0; k0 < CDIM; k0 += BK) {
        // Load A tile (128 rows x 16 cols) -> transposed As[k][m]
        #pragma unroll
        for (int i = 0; i < 2; i++) {
            int f4 = tid + i * 256;       // 512 float4s
            int row = f4 >> 2;            // 4 float4 per row
            int c4 = (f4 & 3) * 4;
            float4 a = *(const float4*)(A + (size_t)(m0 + row) * CDIM + k0 + c4);
            As[(c4 + 0) * AS_STRIDE + row] = a.x;
            As[(c4 + 1) * AS_STRIDE + row] = a.y;
            As[(c4 + 2) * AS_STRIDE + row] = a.z;
            As[(c4 + 3) * AS_STRIDE + row] = a.w;
        }
        // Load B tile (16 rows x 128 cols), coalesced float4
        #pragma unroll
        for (int i = 0; i < 2; i++) {
            int f4 = tid + i * 256;
            int row = f4 >> 5;            // 32 float4 per row
            int c4 = (f4 & 31) * 4;
            *(float4*)(Bs + row * 128 + c4) =
                *(const float4*)(B + (size_t)(k0 + row) * CDIM + n0 + c4);
        }
        __syncthreads();

        #pragma unroll
        for (int k = 0; k < BK; k++) {
            float af[8], bf[8];
            *(float4*)(af)     = *(const float4*)(As + k * AS_STRIDE + ty * 4);
            *(float4*)(af + 4) = *(const float4*)(As + k * AS_STRIDE + 64 + ty * 4);
            *(float4*)(bf)     = *(const float4*)(Bs + k * 128 + tx * 4);
            *(float4*)(bf + 4) = *(const float4*)(Bs + k * 128 + 64 + tx * 4);
            #pragma unroll
            for (int i = 0; i < 8; i++)
                #pragma unroll
                for (int j = 0; j < 8; j++)
                    acc[i][j] = fmaf(af[i], bf[j], acc[i][j]);
        }
        __syncthreads();
    }
}

// ---------------------------------------------------------------------------
// Kernel 1: QKV projections. blockIdx.z: 0->Q, 1->K, 2->V.
// Epilogue writes scratch in [B*H, T, D] (head split folded into index math).
// ---------------------------------------------------------------------------
__global__ __launch_bounds__(256) void qkv_kernel(const float* __restrict__ x,
                                                  const float* __restrict__ Wk,
                                                  const float* __restrict__ Wq,
                                                  const float* __restrict__ Wv) {
    const int m0 = blockIdx.y * 128;
    const int n0 = blockIdx.x * 128;
    const float* W = (blockIdx.z == 0) ? Wq : (blockIdx.z == 1) ? Wk : Wv;
    float* dst = (blockIdx.z == 0) ? g_q : (blockIdx.z == 1) ? g_k : g_v;

    float acc[8][8] = {};
    gemm_body(x, W, m0, n0, acc);

    const int tx = threadIdx.x & 15;
    const int ty = threadIdx.x >> 4;
    #pragma unroll
    for (int i = 0; i < 8; i++) {
        int m = m0 + ((i < 4) ? (ty * 4 + i) : (64 + ty * 4 + i - 4));
        int b = m >> 11;           // /SEQ
        int t = m & (SEQ - 1);
        #pragma unroll
        for (int j = 0; j < 8; j++) {
            int n = n0 + ((j < 4) ? (tx * 4 + j) : (64 + tx * 4 + j - 4));
            int h = n >> 6;
            int d = n & 63;
            dst[(((size_t)(b * NHEADS + h)) * SEQ + t) * HDIM + d] = acc[i][j];
        }
    }
}

// ---------------------------------------------------------------------------
// Kernel 2: causal flash attention, fp32.
// One block per (q-tile of 64 rows, bh). 256 threads, 4x4 micro-tile.
// smem: Qt[d][row] (st 68), KP = Kt[d][col] reused as P[row][kv], Vs[kv][d].
// ---------------------------------------------------------------------------
#define FST 68
#define FBUF (64 * FST)              // 4352 floats
#define FLASH_SMEM (3 * FBUF * 4)    // 52224 bytes

__global__ __launch_bounds__(256) void flash_kernel() {
    extern __shared__ float sm[];
    float* Qt = sm;                  // Qt[d*FST + row]
    float* KP = sm + FBUF;           // Kt[d*FST + col]  /  P[row*FST + kv]
    float* Vs = sm + 2 * FBUF;       // Vs[kv*FST + d]

    const int qt = (QTILES - 1) - blockIdx.x;   // heavy tiles first
    const int bh = blockIdx.y;
    const int tid = threadIdx.x;
    const int tx = tid & 15;
    const int ty = tid >> 4;

    const float* qp = g_q + (size_t)bh * SEQ * HDIM;
    const float* kp = g_k + (size_t)bh * SEQ * HDIM;
    const float* vp = g_v + (size_t)bh * SEQ * HDIM;

    // Load Q tile transposed into Qt
    #pragma unroll
    for (int i = 0; i < 4; i++) {
        int f4 = tid + i * 256;          // 1024 float4 = 64x64 floats
        int row = f4 >> 4;
        int c4 = (f4 & 15) * 4;
        float4 a = *(const float4*)(qp + (size_t)(qt * 64 + row) * HDIM + c4);
        Qt[(c4 + 0) * FST + row] = a.x;
        Qt[(c4 + 1) * FST + row] = a.y;
        Qt[(c4 + 2) * FST + row] = a.z;
        Qt[(c4 + 3) * FST + row] = a.w;
    }

    float m_i[4], l_i[4], o[4][4];
    #pragma unroll
    for (int i = 0; i < 4; i++) {
        m_i[i] = -INFINITY;
        l_i[i] = 0.f;
        #pragma unroll
        for (int j = 0; j < 4; j++) o[i][j] = 0.f;
    }

    for (int kt = 0; kt <= qt; kt++) {
        __syncthreads();   // prior PV reads of KP/Vs done before overwrite
        // Load K (transposed) and V tiles
        #pragma unroll
        for (int i = 0; i < 4; i++) {
            int f4 = tid + i * 256;
            int row = f4 >> 4;
            int c4 = (f4 & 15) * 4;
            float4 a = *(const float4*)(kp + (size_t)(kt * 64 + row) * HDIM + c4);
            KP[(c4 + 0) * FST + row] = a.x;
            KP[(c4 + 1) * FST + row] = a.y;
            KP[(c4 + 2) * FST + row] = a.z;
            KP[(c4 + 3) * FST + row] = a.w;
            float4 b = *(const float4*)(vp + (size_t)(kt * 64 + row) * HDIM + c4);
            *(float4*)(Vs + row * FST + c4) = b;
        }
        __syncthreads();

        // S = Q @ K^T  (4x4 per thread)
        float s[4][4] = {};
        #pragma unroll 8
        for (int d = 0; d < 64; d++) {
            float qa[4], ka[4];
            *(float4*)qa = *(const float4*)(Qt + d * FST + ty * 4);
            *(float4*)ka = *(const float4*)(KP + d * FST + tx * 4);
            #pragma unroll
            for (int i = 0; i < 4; i++)
                #pragma unroll
                for (int j = 0; j < 4; j++)
                    s[i][j] = fmaf(qa[i], ka[j], s[i][j]);
        }

        // scale + causal mask (only the diagonal tile needs masking)
        if (kt == qt) {
            #pragma unroll
            for (int i = 0; i < 4; i++) {
                int r = ty * 4 + i;
                #pragma unroll
                for (int j = 0; j < 4; j++) {
                    int c = tx * 4 + j;
                    s[i][j] = (c <= r) ? s[i][j] * 0.125f : -INFINITY;
                }
            }
        } else {
            #pragma unroll
            for (int i = 0; i < 4; i++)
                #pragma unroll
                for (int j = 0; j < 4; j++) s[i][j] *= 0.125f;
        }

        // online softmax: row groups are 16 contiguous lanes -> shfl reduce
        #pragma unroll
        for (int i = 0; i < 4; i++) {
            float mx = fmaxf(fmaxf(s[i][0], s[i][1]), fmaxf(s[i][2], s[i][3]));
            mx = fmaxf(mx, __shfl_xor_sync(0xffffffffu, mx, 1));
            mx = fmaxf(mx, __shfl_xor_sync(0xffffffffu, mx, 2));
            mx = fmaxf(mx, __shfl_xor_sync(0xffffffffu, mx, 4));
            mx = fmaxf(mx, __shfl_xor_sync(0xffffffffu, mx, 8));
            float mn = fmaxf(m_i[i], mx);
            float alpha = __expf(m_i[i] - mn);
            float rs = 0.f;
            #pragma unroll
            for (int j = 0; j < 4; j++) {
                s[i][j] = __expf(s[i][j] - mn);
                rs += s[i][j];
            }
            rs += __shfl_xor_sync(0xffffffffu, rs, 1);
            rs += __shfl_xor_sync(0xffffffffu, rs, 2);
            rs += __shfl_xor_sync(0xffffffffu, rs, 4);
            rs += __shfl_xor_sync(0xffffffffu, rs, 8);
            l_i[i] = l_i[i] * alpha + rs;
            m_i[i] = mn;
            #pragma unroll
            for (int j = 0; j < 4; j++) o[i][j] *= alpha;
        }

        __syncthreads();   // all S-phase reads of KP (Kt) complete
        // store P row-major into KP buffer (vectorized, conflict-free)
        #pragma unroll
        for (int i = 0; i < 4; i++)
            *(float4*)(KP + (ty * 4 + i) * FST + tx * 4) =
                make_float4(s[i][0], s[i][1], s[i][2], s[i][3]);
        __syncthreads();

        // O += P @ V
        #pragma unroll 8
        for (int kv = 0; kv < 64; kv++) {
            float va[4];
            *(float4*)va = *(const float4*)(Vs + kv * FST + tx * 4);
            float p0 = KP[(ty * 4 + 0) * FST + kv];
            float p1 = KP[(ty * 4 + 1) * FST + kv];
            float p2 = KP[(ty * 4 + 2) * FST + kv];
            float p3 = KP[(ty * 4 + 3) * FST + kv];
            #pragma unroll
            for (int j = 0; j < 4; j++) {
                o[0][j] = fmaf(p0, va[j], o[0][j]);
                o[1][j] = fmaf(p1, va[j], o[1][j]);
                o[2][j] = fmaf(p2, va[j], o[2][j]);
                o[3][j] = fmaf(p3, va[j], o[3][j]);
            }
        }
    }

    // epilogue: normalize and write [B, T, C]
    const int b = bh >> 4;
    const int h = bh & 15;
    #pragma unroll
    for (int i = 0; i < 4; i++) {
        float inv = 1.0f / l_i[i];
        int t = qt * 64 + ty * 4 + i;
        float* op = g_att + ((size_t)(b * SEQ + t)) * CDIM + h * HDIM + tx * 4;
        *(float4*)op = make_float4(o[i][0] * inv, o[i][1] * inv,
                                   o[i][2] * inv, o[i][3] * inv);
    }
}

// ---------------------------------------------------------------------------
// Kernel 3: output projection + bias
// ---------------------------------------------------------------------------
__global__ __launch_bounds__(256) void proj_kernel(const float* __restrict__ Wp,
                                                   const float* __restrict__ bp,
                                                   float* __restrict__ out) {
    const int m0 = blockIdx.y * 128;
    const int n0 = blockIdx.x * 128;
    float acc[8][8] = {};
    gemm_body(g_att, Wp, m0, n0, acc);

    const int tx = threadIdx.x & 15;
    const int ty = threadIdx.x >> 4;
    #pragma unroll
    for (int i = 0; i < 8; i++) {
        int m = m0 + ((i < 4) ? (ty * 4 + i) : (64 + ty * 4 + i - 4));
        #pragma unroll
        for (int j = 0; j < 8; j++) {
            int n = n0 + ((j < 4) ? (tx * 4 + j) : (64 + tx * 4 + j - 4));
            out[(size_t)m * CDIM + n] = acc[i][j] + bp[n];
        }
    }
}

// ---------------------------------------------------------------------------
// Launch: inputs per metadata order: x, Wk, Wq, Wv, Wp, bp
// ---------------------------------------------------------------------------
extern "C" void kernel_launch(void* const* d_in, const int* in_sizes, int n_in,
                              void* d_out, int out_size) {
    (void)in_sizes; (void)n_in; (void)out_size;
    const float* x  = (const float*)d_in[0];
    const float* Wk = (const float*)d_in[1];
    const float* Wq = (const float*)d_in[2];
    const float* Wv = (const float*)d_in[3];
    const float* Wp = (const float*)d_in[4];
    const float* bp = (const float*)d_in[5];
    float* out = (float*)d_out;

    cudaFuncSetAttribute((const void*)flash_kernel,
                         cudaFuncAttributeMaxDynamicSharedMemorySize, FLASH_SMEM);

    dim3 blk(256);
    qkv_kernel<<<dim3(CDIM / 128, BT / 128, 3), blk>>>(x, Wk, Wq, Wv);
    flash_kernel<<<dim3(QTILES, BATCH * NHEADS), blk, FLASH_SMEM>>>();
    proj_kernel<<<dim3(CDIM / 128, BT / 128), blk>>>(Wp, bp, out);
}

// round 3
// speedup vs baseline: 1.2989x; 1.2989x over previous
#include <cuda_runtime.h>
#include <cuda_bf16.h>
#include <math.h>
#include <stdint.h>

// ---------------------------------------------------------------------------
// Problem constants
// ---------------------------------------------------------------------------
#define CDIM 1024
#define NHEADS 16
#define HDIM 64
#define SEQ 2048
#define BATCH 2
#define BT (BATCH * SEQ)     // 4096
#define QTILES (SEQ / 64)    // 32

// ---------------------------------------------------------------------------
// Device scratch (no cudaMalloc allowed)
// ---------------------------------------------------------------------------
__device__ float g_q[BATCH * NHEADS * SEQ * HDIM];
__device__ float g_k[BATCH * NHEADS * SEQ * HDIM];
__device__ float g_v[BATCH * NHEADS * SEQ * HDIM];
__device__ __nv_bfloat16 xs_hi[BT * CDIM];
__device__ __nv_bfloat16 xs_lo[BT * CDIM];
__device__ __nv_bfloat16 at_hi[BT * CDIM];
__device__ __nv_bfloat16 at_lo[BT * CDIM];
__device__ __nv_bfloat16 wt_hi[4 * CDIM * CDIM];   // W^T, slots: 0=Wq 1=Wk 2=Wv 3=Wp
__device__ __nv_bfloat16 wt_lo[4 * CDIM * CDIM];

// ---------------------------------------------------------------------------
// PTX helpers (sm_100-safe: no tcgen05, no 'a'-suffix features)
// ---------------------------------------------------------------------------
__device__ __forceinline__ uint32_t smem_u32(const void* p) {
    uint32_t a;
    asm("{ .reg .u64 t; cvta.to.shared.u64 t, %1; cvt.u32.u64 %0, t; }" : "=r"(a) : "l"(p));
    return a;
}

#define CPA(saddr, gptr) \
    asm volatile("cp.async.cg.shared.global [%0], [%1], 16;" :: "r"(saddr), "l"(gptr) : "memory")
#define CPC() asm volatile("cp.async.commit_group;" ::: "memory")
#define CPW1() asm volatile("cp.async.wait_group 1;" ::: "memory")
#define CPW0() asm volatile("cp.async.wait_group 0;" ::: "memory")

#define LDSM4(r, a) \
    asm volatile("ldmatrix.sync.aligned.m8n8.x4.shared.b16 {%0,%1,%2,%3}, [%4];" \
        : "=r"((r)[0]), "=r"((r)[1]), "=r"((r)[2]), "=r"((r)[3]) : "r"(a))

#define MMA16816(d, a, b0, b1) \
    asm volatile("mma.sync.aligned.m16n8k16.row.col.f32.bf16.bf16.f32 " \
        "{%0,%1,%2,%3}, {%4,%5,%6,%7}, {%8,%9}, {%0,%1,%2,%3};" \
        : "+f"((d)[0]), "+f"((d)[1]), "+f"((d)[2]), "+f"((d)[3]) \
        : "r"((a)[0]), "r"((a)[1]), "r"((a)[2]), "r"((a)[3]), "r"(b0), "r"(b1))

// ---------------------------------------------------------------------------
// Conversion kernels: fp32 -> bf16 hi/lo split
// ---------------------------------------------------------------------------
__global__ __launch_bounds__(256) void split_kernel(const float* __restrict__ src,
                                                    __nv_bfloat16* __restrict__ hi,
                                                    __nv_bfloat16* __restrict__ lo) {
    int i = blockIdx.x * 256 + threadIdx.x;     // one 8-float group per thread
    const float4* s = (const float4*)src + (size_t)i * 2;
    float4 a = s[0], b = s[1];
    float v[8] = {a.x, a.y, a.z, a.w, b.x, b.y, b.z, b.w};
    __nv_bfloat162 h[4], l[4];
    #pragma unroll
    for (int j = 0; j < 4; j++) {
        h[j] = __floats2bfloat162_rn(v[2*j], v[2*j+1]);
        l[j] = __floats2bfloat162_rn(v[2*j]   - __bfloat162float(h[j].x),
                                     v[2*j+1] - __bfloat162float(h[j].y));
    }
    __nv_bfloat162* hp = (__nv_bfloat162*)(hi + (size_t)i * 8);
    __nv_bfloat162* lp = (__nv_bfloat162*)(lo + (size_t)i * 8);
    #pragma unroll
    for (int j = 0; j < 4; j++) { hp[j] = h[j]; lp[j] = l[j]; }
}

// W [k][n] fp32 -> W^T [n][k] bf16 hi/lo, slot per blockIdx.z
__global__ __launch_bounds__(256) void wt_kernel(const float* __restrict__ Wq,
                                                 const float* __restrict__ Wk,
                                                 const float* __restrict__ Wv,
                                                 const float* __restrict__ Wp) {
    __shared__ float t[32][33];
    int z = blockIdx.z;
    const float* W = (z == 0) ? Wq : (z == 1) ? Wk : (z == 2) ? Wv : Wp;
    int n0 = blockIdx.x * 32, k0 = blockIdx.y * 32;
    int tx = threadIdx.x & 31, ty = threadIdx.x >> 5;   // 32 x 8
    #pragma unroll
    for (int p = 0; p < 4; p++)
        t[ty + 8 * p][tx] = W[(size_t)(k0 + ty + 8 * p) * CDIM + n0 + tx];
    __syncthreads();
    size_t base = (size_t)z * CDIM * CDIM;
    #pragma unroll
    for (int p = 0; p < 4; p++) {
        int n = n0 + ty + 8 * p, k = k0 + tx;
        float v = t[tx][ty + 8 * p];
        __nv_bfloat16 h = __float2bfloat16(v);
        __nv_bfloat16 l = __float2bfloat16(v - __bfloat162float(h));
        wt_hi[base + (size_t)n * CDIM + k] = h;
        wt_lo[base + (size_t)n * CDIM + k] = l;
    }
}

// ---------------------------------------------------------------------------
// Tensor-core GEMM (mma.sync bf16, 3-term hi/lo split, fp32 accum).
// C[4096 x 1024] = A * W^T(slot).  Block tile 128x128, BK=32, 8 warps (64x32).
// mode 0: A = xs   -> g_q/g_k/g_v [B*H, T, D]  (z picks W/dst)
// mode 1: A = att  -> out = A*Wp + bp
// ---------------------------------------------------------------------------
#define BKC 32
#define NSTG (CDIM / BKC)        // 32 k-chunks
#define ROWB 80                  // smem row stride bytes (32 bf16 + 8 pad)
#define TILE_B (128 * ROWB)      // 10240 B
#define STAGE_B (4 * TILE_B)     // 40960 B : Ahi, Alo, Bhi, Blo
#define MM_SMEM (2 * STAGE_B)    // 81920 B

__global__ __launch_bounds__(256, 1) void mm_kernel(int mode, const float* __restrict__ bp,
                                                    float* __restrict__ out) {
    extern __shared__ char sm[];
    const uint32_t smb = smem_u32(sm);
    const int tid = threadIdx.x;
    const int lane = tid & 31;
    const int w = tid >> 5;
    const int wm = (w >> 2) * 64;        // warp m offset (2 warps)
    const int wn = (w & 3) * 32;         // warp n offset (4 warps)
    const int n0 = blockIdx.x * 128;
    const int m0 = blockIdx.y * 128;

    const __nv_bfloat16* Ah = mode ? at_hi : xs_hi;
    const __nv_bfloat16* Al = mode ? at_lo : xs_lo;
    const int wz = mode ? 3 : blockIdx.z;
    const size_t wbase = (size_t)wz * CDIM * CDIM;

    // per-thread load slots: idx -> (row, 16B chunk)
    const int r0 = tid >> 2, c0 = (tid & 3);          // first slot
    const int r1 = (tid + 256) >> 2;                  // second slot (chunk same c0)

    float acc[4][4][4];
    #pragma unroll
    for (int i = 0; i < 4; i++)
        #pragma unroll
        for (int j = 0; j < 4; j++)
            #pragma unroll
            for (int q = 0; q < 4; q++) acc[i][j][q] = 0.f;

    // ---- async stage loader ----
    auto load_stage = [&](int s, int c) {
        const int k0 = c * BKC;
        const uint32_t sb = smb + s * STAGE_B;
        const uint32_t so0 = r0 * ROWB + c0 * 16;
        const uint32_t so1 = r1 * ROWB + c0 * 16;
        const size_t gA0 = (size_t)(m0 + r0) * CDIM + k0 + c0 * 8;
        const size_t gA1 = (size_t)(m0 + r1) * CDIM + k0 + c0 * 8;
        const size_t gB0 = wbase + (size_t)(n0 + r0) * CDIM + k0 + c0 * 8;
        const size_t gB1 = wbase + (size_t)(n0 + r1) * CDIM + k0 + c0 * 8;
        CPA(sb + so0,              Ah + gA0);
        CPA(sb + so1,              Ah + gA1);
        CPA(sb + TILE_B + so0,     Al + gA0);
        CPA(sb + TILE_B + so1,     Al + gA1);
        CPA(sb + 2 * TILE_B + so0, wt_hi + gB0);
        CPA(sb + 2 * TILE_B + so1, wt_hi + gB1);
        CPA(sb + 3 * TILE_B + so0, wt_lo + gB0);
        CPA(sb + 3 * TILE_B + so1, wt_lo + gB1);
    };

    load_stage(0, 0);
    CPC();

    const int fr = lane & 15;            // fragment row
    const int fc = lane >> 4;            // fragment col8 (0/1)

    for (int c = 0; c < NSTG; c++) {
        const int s = c & 1;
        if (c + 1 < NSTG) { load_stage(s ^ 1, c + 1); CPC(); CPW1(); }
        else              { CPW0(); }
        __syncthreads();

        const uint32_t sb = smb + s * STAGE_B;
        #pragma unroll
        for (int k16 = 0; k16 < 2; k16++) {
            const uint32_t kofs = k16 * 32 + fc * 16;
            uint32_t af[4][4], bh[2][4], bl[2][4];
            // A hi
            #pragma unroll
            for (int mt = 0; mt < 4; mt++)
                LDSM4(af[mt], sb + (wm + mt * 16 + fr) * ROWB + kofs);
            // B hi, B lo
            #pragma unroll
            for (int bt = 0; bt < 2; bt++) {
                LDSM4(bh[bt], sb + 2 * TILE_B + (wn + bt * 16 + fr) * ROWB + kofs);
                LDSM4(bl[bt], sb + 3 * TILE_B + (wn + bt * 16 + fr) * ROWB + kofs);
            }
            // term 1: hi*hi
            #pragma unroll
            for (int mt = 0; mt < 4; mt++)
                #pragma unroll
                for (int nt = 0; nt < 4; nt++)
                    MMA16816(acc[mt][nt], af[mt], bh[nt >> 1][nt & 1], bh[nt >> 1][(nt & 1) + 2]);
            // term 2: hi*lo
            #pragma unroll
            for (int mt = 0; mt < 4; mt++)
                #pragma unroll
                for (int nt = 0; nt < 4; nt++)
                    MMA16816(acc[mt][nt], af[mt], bl[nt >> 1][nt & 1], bl[nt >> 1][(nt & 1) + 2]);
            // A lo (reuse regs), term 3: lo*hi
            #pragma unroll
            for (int mt = 0; mt < 4; mt++)
                LDSM4(af[mt], sb + TILE_B + (wm + mt * 16 + fr) * ROWB + kofs);
            #pragma unroll
            for (int mt = 0; mt < 4; mt++)
                #pragma unroll
                for (int nt = 0; nt < 4; nt++)
                    MMA16816(acc[mt][nt], af[mt], bh[nt >> 1][nt & 1], bh[nt >> 1][(nt & 1) + 2]);
        }
        __syncthreads();
    }

    // ---- epilogue: direct float2 stores (quad-contiguous 32B sectors) ----
    float* dst0 = (mode == 0) ? ((blockIdx.z == 0) ? g_q : (blockIdx.z == 1) ? g_k : g_v) : out;
    #pragma unroll
    for (int mt = 0; mt < 4; mt++) {
        #pragma unroll
        for (int nt = 0; nt < 4; nt++) {
            int m = m0 + wm + mt * 16 + (lane >> 2);
            int n = n0 + wn + nt * 8 + (lane & 3) * 2;
            float2 v0 = make_float2(acc[mt][nt][0], acc[mt][nt][1]);   // row m
            float2 v1 = make_float2(acc[mt][nt][2], acc[mt][nt][3]);   // row m+8
            if (mode == 0) {
                int h = n >> 6, d = n & 63;
                int b = m >> 11, t = m & (SEQ - 1);
                size_t hb = ((size_t)(b * NHEADS + h) * SEQ);
                *(float2*)(dst0 + ((hb + t) << 6) + d) = v0;
                int m2 = m + 8;
                int b2 = m2 >> 11, t2 = m2 & (SEQ - 1);
                size_t hb2 = ((size_t)(b2 * NHEADS + h) * SEQ);
                *(float2*)(dst0 + ((hb2 + t2) << 6) + d) = v1;
            } else {
                float bx = bp[n], by = bp[n + 1];
                v0.x += bx; v0.y += by;
                v1.x += bx; v1.y += by;
                *(float2*)(dst0 + (size_t)m * CDIM + n) = v0;
                *(float2*)(dst0 + (size_t)(m + 8) * CDIM + n) = v1;
            }
        }
    }
}

// ---------------------------------------------------------------------------
// Causal flash attention, fp32 SIMT (round-1 math; epilogue emits bf16 hi/lo)
// ---------------------------------------------------------------------------
#define FST 68
#define FBUF (64 * FST)
#define FLASH_SMEM (3 * FBUF * 4)

__global__ __launch_bounds__(256) void flash_kernel() {
    extern __shared__ char smc[];
    float* smf = (float*)smc;
    float* Qt = smf;
    float* KP = smf + FBUF;
    float* Vs = smf + 2 * FBUF;

    const int qt = (QTILES - 1) - blockIdx.x;
    const int bh = blockIdx.y;
    const int tid = threadIdx.x;
    const int tx = tid & 15;
    const int ty = tid >> 4;

    const float* qp = g_q + (size_t)bh * SEQ * HDIM;
    const float* kp = g_k + (size_t)bh * SEQ * HDIM;
    const float* vp = g_v + (size_t)bh * SEQ * HDIM;

    #pragma unroll
    for (int i = 0; i < 4; i++) {
        int f4 = tid + i * 256;
        int row = f4 >> 4;
        int c4 = (f4 & 15) * 4;
        float4 a = *(const float4*)(qp + (size_t)(qt * 64 + row) * HDIM + c4);
        Qt[(c4 + 0) * FST + row] = a.x;
        Qt[(c4 + 1) * FST + row] = a.y;
        Qt[(c4 + 2) * FST + row] = a.z;
        Qt[(c4 + 3) * FST + row] = a.w;
    }

    float m_i[4], l_i[4], o[4][4];
    #pragma unroll
    for (int i = 0; i < 4; i++) {
        m_i[i] = -INFINITY; l_i[i] = 0.f;
        #pragma unroll
        for (int j = 0; j < 4; j++) o[i][j] = 0.f;
    }

    for (int kt = 0; kt <= qt; kt++) {
        __syncthreads();
        #pragma unroll
        for (int i = 0; i < 4; i++) {
            int f4 = tid + i * 256;
            int row = f4 >> 4;
            int c4 = (f4 & 15) * 4;
            float4 a = *(const float4*)(kp + (size_t)(kt * 64 + row) * HDIM + c4);
            KP[(c4 + 0) * FST + row] = a.x;
            KP[(c4 + 1) * FST + row] = a.y;
            KP[(c4 + 2) * FST + row] = a.z;
            KP[(c4 + 3) * FST + row] = a.w;
            float4 b = *(const float4*)(vp + (size_t)(kt * 64 + row) * HDIM + c4);
            *(float4*)(Vs + row * FST + c4) = b;
        }
        __syncthreads();

        float s[4][4] = {};
        #pragma unroll 8
        for (int d = 0; d < 64; d++) {
            float qa[4], ka[4];
            *(float4*)qa = *(const float4*)(Qt + d * FST + ty * 4);
            *(float4*)ka = *(const float4*)(KP + d * FST + tx * 4);
            #pragma unroll
            for (int i = 0; i < 4; i++)
                #pragma unroll
                for (int j = 0; j < 4; j++)
                    s[i][j] = fmaf(qa[i], ka[j], s[i][j]);
        }

        if (kt == qt) {
            #pragma unroll
            for (int i = 0; i < 4; i++) {
                int rrow = ty * 4 + i;
                #pragma unroll
                for (int j = 0; j < 4; j++) {
                    int ccol = tx * 4 + j;
                    s[i][j] = (ccol <= rrow) ? s[i][j] * 0.125f : -INFINITY;
                }
            }
        } else {
            #pragma unroll
            for (int i = 0; i < 4; i++)
                #pragma unroll
                for (int j = 0; j < 4; j++) s[i][j] *= 0.125f;
        }

        #pragma unroll
        for (int i = 0; i < 4; i++) {
            float mx = fmaxf(fmaxf(s[i][0], s[i][1]), fmaxf(s[i][2], s[i][3]));
            mx = fmaxf(mx, __shfl_xor_sync(0xffffffffu, mx, 1));
            mx = fmaxf(mx, __shfl_xor_sync(0xffffffffu, mx, 2));
            mx = fmaxf(mx, __shfl_xor_sync(0xffffffffu, mx, 4));
            mx = fmaxf(mx, __shfl_xor_sync(0xffffffffu, mx, 8));
            float mn = fmaxf(m_i[i], mx);
            float alpha = __expf(m_i[i] - mn);
            float rs = 0.f;
            #pragma unroll
            for (int j = 0; j < 4; j++) { s[i][j] = __expf(s[i][j] - mn); rs += s[i][j]; }
            rs += __shfl_xor_sync(0xffffffffu, rs, 1);
            rs += __shfl_xor_sync(0xffffffffu, rs, 2);
            rs += __shfl_xor_sync(0xffffffffu, rs, 4);
            rs += __shfl_xor_sync(0xffffffffu, rs, 8);
            l_i[i] = l_i[i] * alpha + rs;
            m_i[i] = mn;
            #pragma unroll
            for (int j = 0; j < 4; j++) o[i][j] *= alpha;
        }

        __syncthreads();
        #pragma unroll
        for (int i = 0; i < 4; i++)
            *(float4*)(KP + (ty * 4 + i) * FST + tx * 4) =
                make_float4(s[i][0], s[i][1], s[i][2], s[i][3]);
        __syncthreads();

        #pragma unroll 8
        for (int kv = 0; kv < 64; kv++) {
            float va[4];
            *(float4*)va = *(const float4*)(Vs + kv * FST + tx * 4);
            float p0 = KP[(ty * 4 + 0) * FST + kv];
            float p1 = KP[(ty * 4 + 1) * FST + kv];
            float p2 = KP[(ty * 4 + 2) * FST + kv];
            float p3 = KP[(ty * 4 + 3) * FST + kv];
            #pragma unroll
            for (int j = 0; j < 4; j++) {
                o[0][j] = fmaf(p0, va[j], o[0][j]);
                o[1][j] = fmaf(p1, va[j], o[1][j]);
                o[2][j] = fmaf(p2, va[j], o[2][j]);
                o[3][j] = fmaf(p3, va[j], o[3][j]);
            }
        }
    }

    // epilogue: normalize, split to bf16 hi/lo for the proj GEMM
    const int b = bh >> 4;
    const int h = bh & 15;
    #pragma unroll
    for (int i = 0; i < 4; i++) {
        float inv = 1.0f / l_i[i];
        int t = qt * 64 + ty * 4 + i;
        float v0 = o[i][0] * inv, v1 = o[i][1] * inv, v2 = o[i][2] * inv, v3 = o[i][3] * inv;
        size_t base = ((size_t)(b * SEQ + t)) * CDIM + h * HDIM + tx * 4;
        __nv_bfloat162 h01 = __floats2bfloat162_rn(v0, v1);
        __nv_bfloat162 h23 = __floats2bfloat162_rn(v2, v3);
        __nv_bfloat162 l01 = __floats2bfloat162_rn(v0 - __bfloat162float(h01.x),
                                                   v1 - __bfloat162float(h01.y));
        __nv_bfloat162 l23 = __floats2bfloat162_rn(v2 - __bfloat162float(h23.x),
                                                   v3 - __bfloat162float(h23.y));
        *(__nv_bfloat162*)(at_hi + base)     = h01;
        *(__nv_bfloat162*)(at_hi + base + 2) = h23;
        *(__nv_bfloat162*)(at_lo + base)     = l01;
        *(__nv_bfloat162*)(at_lo + base + 2) = l23;
    }
}

// ---------------------------------------------------------------------------
// Launch: inputs x, Wk, Wq, Wv, Wp, bp
// ---------------------------------------------------------------------------
extern "C" void kernel_launch(void* const* d_in, const int* in_sizes, int n_in,
                              void* d_out, int out_size) {
    (void)in_sizes; (void)n_in; (void)out_size;
    const float* x  = (const float*)d_in[0];
    const float* Wk = (const float*)d_in[1];
    const float* Wq = (const float*)d_in[2];
    const float* Wv = (const float*)d_in[3];
    const float* Wp = (const float*)d_in[4];
    const float* bp = (const float*)d_in[5];
    float* out = (float*)d_out;

    cudaFuncSetAttribute((const void*)mm_kernel,
                         cudaFuncAttributeMaxDynamicSharedMemorySize, MM_SMEM);
    cudaFuncSetAttribute((const void*)flash_kernel,
                         cudaFuncAttributeMaxDynamicSharedMemorySize, FLASH_SMEM);

    __nv_bfloat16 *xh, *xl;
    cudaGetSymbolAddress((void**)&xh, xs_hi);
    cudaGetSymbolAddress((void**)&xl, xs_lo);

    split_kernel<<<(BT * CDIM) / (256 * 8), 256>>>(x, xh, xl);
    wt_kernel<<<dim3(32, 32, 4), 256>>>(Wq, Wk, Wv, Wp);
    mm_kernel<<<dim3(CDIM / 128, BT / 128, 3), 256, MM_SMEM>>>(0, nullptr, nullptr);
    flash_kernel<<<dim3(QTILES, BATCH * NHEADS), 256, FLASH_SMEM>>>();
    mm_kernel<<<dim3(CDIM / 128, BT / 128, 1), 256, MM_SMEM>>>(1, bp, out);
}

// round 4
// speedup vs baseline: 2.1737x; 1.6735x over previous
#include <cuda_runtime.h>
#include <cuda_bf16.h>
#include <math.h>
#include <stdint.h>

// ---------------------------------------------------------------------------
// Problem constants
// ---------------------------------------------------------------------------
#define CDIM 1024
#define NHEADS 16
#define HDIM 64
#define SEQ 2048
#define BATCH 2
#define BT (BATCH * SEQ)     // 4096
#define NBH (BATCH * NHEADS) // 32

// ---------------------------------------------------------------------------
// Device scratch (no cudaMalloc allowed)
// ---------------------------------------------------------------------------
__device__ __nv_bfloat16 xs_hi[BT * CDIM];
__device__ __nv_bfloat16 xs_lo[BT * CDIM];
__device__ __nv_bfloat16 at_hi[BT * CDIM];
__device__ __nv_bfloat16 at_lo[BT * CDIM];
__device__ __nv_bfloat16 wt_hi[4 * CDIM * CDIM];   // W^T, slots: 0=Wq 1=Wk 2=Wv 3=Wp
__device__ __nv_bfloat16 wt_lo[4 * CDIM * CDIM];
// attention operands (bf16 hi/lo): Q,K in [bh][t][d]; V transposed [bh][d][t]
__device__ __nv_bfloat16 q_hi[NBH * SEQ * HDIM];
__device__ __nv_bfloat16 q_lo[NBH * SEQ * HDIM];
__device__ __nv_bfloat16 k_hi[NBH * SEQ * HDIM];
__device__ __nv_bfloat16 k_lo[NBH * SEQ * HDIM];
__device__ __nv_bfloat16 vt_hi[NBH * HDIM * SEQ];
__device__ __nv_bfloat16 vt_lo[NBH * HDIM * SEQ];

// ---------------------------------------------------------------------------
// PTX helpers (sm_100-safe)
// ---------------------------------------------------------------------------
__device__ __forceinline__ uint32_t smem_u32(const void* p) {
    uint32_t a;
    asm("{ .reg .u64 t; cvta.to.shared.u64 t, %1; cvt.u32.u64 %0, t; }" : "=r"(a) : "l"(p));
    return a;
}

#define CPA(saddr, gptr) \
    asm volatile("cp.async.cg.shared.global [%0], [%1], 16;" :: "r"(saddr), "l"(gptr) : "memory")
#define CPC() asm volatile("cp.async.commit_group;" ::: "memory")
#define CPW1() asm volatile("cp.async.wait_group 1;" ::: "memory")
#define CPW0() asm volatile("cp.async.wait_group 0;" ::: "memory")

#define LDSM4(r, a) \
    asm volatile("ldmatrix.sync.aligned.m8n8.x4.shared.b16 {%0,%1,%2,%3}, [%4];" \
        : "=r"((r)[0]), "=r"((r)[1]), "=r"((r)[2]), "=r"((r)[3]) : "r"(a))

#define MMA16816(d, a, b0, b1) \
    asm volatile("mma.sync.aligned.m16n8k16.row.col.f32.bf16.bf16.f32 " \
        "{%0,%1,%2,%3}, {%4,%5,%6,%7}, {%8,%9}, {%0,%1,%2,%3};" \
        : "+f"((d)[0]), "+f"((d)[1]), "+f"((d)[2]), "+f"((d)[3]) \
        : "r"((a)[0]), "r"((a)[1]), "r"((a)[2]), "r"((a)[3]), "r"(b0), "r"(b1))

__device__ __forceinline__ uint32_t pk_hi(float x, float y) {
    __nv_bfloat162 t = __floats2bfloat162_rn(x, y);
    return *(uint32_t*)&t;
}
__device__ __forceinline__ uint32_t pk_lo(float x, float y, uint32_t hi) {
    __nv_bfloat162 h = *(__nv_bfloat162*)&hi;
    __nv_bfloat162 t = __floats2bfloat162_rn(x - __bfloat162float(h.x),
                                             y - __bfloat162float(h.y));
    return *(uint32_t*)&t;
}

// ---------------------------------------------------------------------------
// fp32 -> bf16 hi/lo split (for x)
// ---------------------------------------------------------------------------
__global__ __launch_bounds__(256) void split_kernel(const float* __restrict__ src,
                                                    __nv_bfloat16* __restrict__ hi,
                                                    __nv_bfloat16* __restrict__ lo) {
    int i = blockIdx.x * 256 + threadIdx.x;
    const float4* s = (const float4*)src + (size_t)i * 2;
    float4 a = s[0], b = s[1];
    float v[8] = {a.x, a.y, a.z, a.w, b.x, b.y, b.z, b.w};
    __nv_bfloat162 h[4], l[4];
    #pragma unroll
    for (int j = 0; j < 4; j++) {
        h[j] = __floats2bfloat162_rn(v[2*j], v[2*j+1]);
        l[j] = __floats2bfloat162_rn(v[2*j]   - __bfloat162float(h[j].x),
                                     v[2*j+1] - __bfloat162float(h[j].y));
    }
    __nv_bfloat162* hp = (__nv_bfloat162*)(hi + (size_t)i * 8);
    __nv_bfloat162* lp = (__nv_bfloat162*)(lo + (size_t)i * 8);
    #pragma unroll
    for (int j = 0; j < 4; j++) { hp[j] = h[j]; lp[j] = l[j]; }
}

// W [k][n] fp32 -> W^T [n][k] bf16 hi/lo
__global__ __launch_bounds__(256) void wt_kernel(const float* __restrict__ Wq,
                                                 const float* __restrict__ Wk,
                                                 const float* __restrict__ Wv,
                                                 const float* __restrict__ Wp) {
    __shared__ float t[32][33];
    int z = blockIdx.z;
    const float* W = (z == 0) ? Wq : (z == 1) ? Wk : (z == 2) ? Wv : Wp;
    int n0 = blockIdx.x * 32, k0 = blockIdx.y * 32;
    int tx = threadIdx.x & 31, ty = threadIdx.x >> 5;
    #pragma unroll
    for (int p = 0; p < 4; p++)
        t[ty + 8 * p][tx] = W[(size_t)(k0 + ty + 8 * p) * CDIM + n0 + tx];
    __syncthreads();
    size_t base = (size_t)z * CDIM * CDIM;
    #pragma unroll
    for (int p = 0; p < 4; p++) {
        int n = n0 + ty + 8 * p, k = k0 + tx;
        float v = t[tx][ty + 8 * p];
        __nv_bfloat16 h = __float2bfloat16(v);
        __nv_bfloat16 l = __float2bfloat16(v - __bfloat162float(h));
        wt_hi[base + (size_t)n * CDIM + k] = h;
        wt_lo[base + (size_t)n * CDIM + k] = l;
    }
}

// ---------------------------------------------------------------------------
// Tensor-core GEMM (mma.sync bf16, 3-term split). 128x128 tile, BK=32, 8 warps.
// mode 0: A=xs -> q/k bf16 hi/lo [bh][t][d], v transposed [bh][d][t]
// mode 1: A=at -> out = A*Wp + bp (fp32)
// ---------------------------------------------------------------------------
#define BKC 32
#define NSTG (CDIM / BKC)
#define ROWB 80
#define TILE_B (128 * ROWB)
#define STAGE_B (4 * TILE_B)
#define MM_SMEM (2 * STAGE_B)

__global__ __launch_bounds__(256, 1) void mm_kernel(int mode, const float* __restrict__ bp,
                                                    float* __restrict__ out) {
    extern __shared__ char sm[];
    const uint32_t smb = smem_u32(sm);
    const int tid = threadIdx.x;
    const int lane = tid & 31;
    const int w = tid >> 5;
    const int wm = (w >> 2) * 64;
    const int wn = (w & 3) * 32;
    const int n0 = blockIdx.x * 128;
    const int m0 = blockIdx.y * 128;

    const __nv_bfloat16* Ah = mode ? at_hi : xs_hi;
    const __nv_bfloat16* Al = mode ? at_lo : xs_lo;
    const int wz = mode ? 3 : blockIdx.z;
    const size_t wbase = (size_t)wz * CDIM * CDIM;

    const int r0 = tid >> 2, c0 = (tid & 3);
    const int r1 = (tid + 256) >> 2;

    float acc[4][4][4];
    #pragma unroll
    for (int i = 0; i < 4; i++)
        #pragma unroll
        for (int j = 0; j < 4; j++)
            #pragma unroll
            for (int q = 0; q < 4; q++) acc[i][j][q] = 0.f;

    auto load_stage = [&](int s, int c) {
        const int k0 = c * BKC;
        const uint32_t sb = smb + s * STAGE_B;
        const uint32_t so0 = r0 * ROWB + c0 * 16;
        const uint32_t so1 = r1 * ROWB + c0 * 16;
        const size_t gA0 = (size_t)(m0 + r0) * CDIM + k0 + c0 * 8;
        const size_t gA1 = (size_t)(m0 + r1) * CDIM + k0 + c0 * 8;
        const size_t gB0 = wbase + (size_t)(n0 + r0) * CDIM + k0 + c0 * 8;
        const size_t gB1 = wbase + (size_t)(n0 + r1) * CDIM + k0 + c0 * 8;
        CPA(sb + so0,              Ah + gA0);
        CPA(sb + so1,              Ah + gA1);
        CPA(sb + TILE_B + so0,     Al + gA0);
        CPA(sb + TILE_B + so1,     Al + gA1);
        CPA(sb + 2 * TILE_B + so0, wt_hi + gB0);
        CPA(sb + 2 * TILE_B + so1, wt_hi + gB1);
        CPA(sb + 3 * TILE_B + so0, wt_lo + gB0);
        CPA(sb + 3 * TILE_B + so1, wt_lo + gB1);
    };

    load_stage(0, 0);
    CPC();

    const int fr = lane & 15;
    const int fc = lane >> 4;

    for (int c = 0; c < NSTG; c++) {
        const int s = c & 1;
        if (c + 1 < NSTG) { load_stage(s ^ 1, c + 1); CPC(); CPW1(); }
        else              { CPW0(); }
        __syncthreads();

        const uint32_t sb = smb + s * STAGE_B;
        #pragma unroll
        for (int k16 = 0; k16 < 2; k16++) {
            const uint32_t kofs = k16 * 32 + fc * 16;
            uint32_t af[4][4], bh[2][4], bl[2][4];
            #pragma unroll
            for (int mt = 0; mt < 4; mt++)
                LDSM4(af[mt], sb + (wm + mt * 16 + fr) * ROWB + kofs);
            #pragma unroll
            for (int bt = 0; bt < 2; bt++) {
                LDSM4(bh[bt], sb + 2 * TILE_B + (wn + bt * 16 + fr) * ROWB + kofs);
                LDSM4(bl[bt], sb + 3 * TILE_B + (wn + bt * 16 + fr) * ROWB + kofs);
            }
            #pragma unroll
            for (int mt = 0; mt < 4; mt++)
                #pragma unroll
                for (int nt = 0; nt < 4; nt++)
                    MMA16816(acc[mt][nt], af[mt], bh[nt >> 1][nt & 1], bh[nt >> 1][(nt & 1) + 2]);
            #pragma unroll
            for (int mt = 0; mt < 4; mt++)
                #pragma unroll
                for (int nt = 0; nt < 4; nt++)
                    MMA16816(acc[mt][nt], af[mt], bl[nt >> 1][nt & 1], bl[nt >> 1][(nt & 1) + 2]);
            #pragma unroll
            for (int mt = 0; mt < 4; mt++)
                LDSM4(af[mt], sb + TILE_B + (wm + mt * 16 + fr) * ROWB + kofs);
            #pragma unroll
            for (int mt = 0; mt < 4; mt++)
                #pragma unroll
                for (int nt = 0; nt < 4; nt++)
                    MMA16816(acc[mt][nt], af[mt], bh[nt >> 1][nt & 1], bh[nt >> 1][(nt & 1) + 2]);
        }
        __syncthreads();
    }

    // ---- epilogue ----
    if (mode == 1) {
        #pragma unroll
        for (int mt = 0; mt < 4; mt++) {
            #pragma unroll
            for (int nt = 0; nt < 4; nt++) {
                int m = m0 + wm + mt * 16 + (lane >> 2);
                int n = n0 + wn + nt * 8 + (lane & 3) * 2;
                float bx = bp[n], by = bp[n + 1];
                *(float2*)(out + (size_t)m * CDIM + n) =
                    make_float2(acc[mt][nt][0] + bx, acc[mt][nt][1] + by);
                *(float2*)(out + (size_t)(m + 8) * CDIM + n) =
                    make_float2(acc[mt][nt][2] + bx, acc[mt][nt][3] + by);
            }
        }
    } else {
        const int z = blockIdx.z;
        __nv_bfloat16* dh = (z == 0) ? q_hi : (z == 1) ? k_hi : vt_hi;
        __nv_bfloat16* dl = (z == 0) ? q_lo : (z == 1) ? k_lo : vt_lo;
        #pragma unroll
        for (int mt = 0; mt < 4; mt++) {
            #pragma unroll
            for (int nt = 0; nt < 4; nt++) {
                int m = m0 + wm + mt * 16 + (lane >> 2);
                int n = n0 + wn + nt * 8 + (lane & 3) * 2;
                int b = m >> 11, t = m & (SEQ - 1);
                int h = n >> 6, d = n & 63;
                int bh = b * NHEADS + h;
                float v0 = acc[mt][nt][0], v1 = acc[mt][nt][1];
                float v2 = acc[mt][nt][2], v3 = acc[mt][nt][3];
                uint32_t h01 = pk_hi(v0, v1), l01 = pk_lo(v0, v1, h01);
                uint32_t h23 = pk_hi(v2, v3), l23 = pk_lo(v2, v3, h23);
                if (z < 2) {
                    size_t i0 = ((size_t)bh * SEQ + t) * HDIM + d;
                    *(uint32_t*)(dh + i0) = h01;
                    *(uint32_t*)(dl + i0) = l01;
                    size_t i1 = i0 + 8 * HDIM;    // row m+8
                    *(uint32_t*)(dh + i1) = h23;
                    *(uint32_t*)(dl + i1) = l23;
                } else {
                    // transposed store: vt[bh][d][t]
                    size_t i0 = ((size_t)bh * HDIM + d) * SEQ + t;
                    __nv_bfloat162 H01 = *(__nv_bfloat162*)&h01, L01 = *(__nv_bfloat162*)&l01;
                    __nv_bfloat162 H23 = *(__nv_bfloat162*)&h23, L23 = *(__nv_bfloat162*)&l23;
                    dh[i0] = H01.x;        dl[i0] = L01.x;          // (d,   t)
                    dh[i0 + SEQ] = H01.y;  dl[i0 + SEQ] = L01.y;    // (d+1, t)
                    dh[i0 + 8] = H23.x;    dl[i0 + 8] = L23.x;      // (d,   t+8)
                    dh[i0 + SEQ + 8] = H23.y; dl[i0 + SEQ + 8] = L23.y;
                }
            }
        }
    }
}

// ---------------------------------------------------------------------------
// Tensor-core causal flash attention.
// Block = (bh, 128 q-rows). 8 warps, each owns m16 x n64 S-tile per kv chunk
// of 64. 3-term bf16 hi/lo split on S and PV; softmax fp32 in registers.
// smem: Qh 16K | Ql 16K | stage{0,1}: Kh 8K Kl 8K Vh 8K Vl 8K
// ---------------------------------------------------------------------------
#define FL_SMEM 98304
#define SOFT_SCALE 0.125f

__global__ __launch_bounds__(256) void flash_kernel() {
    extern __shared__ char smc[];
    const uint32_t smb = smem_u32(smc);
    const int tid = threadIdx.x;
    const int lane = tid & 31;
    const int w = tid >> 5;
    const int qt = (gridDim.x - 1) - blockIdx.x;   // heavy first
    const int bh = blockIdx.y;
    const int q0 = qt * 128;
    const size_t qkb = (size_t)bh * SEQ * HDIM;
    const size_t vtb = (size_t)bh * HDIM * SEQ;

    // Q loads (hi+lo), 1024 chunks each, 4 per thread per component
    #pragma unroll
    for (int i = 0; i < 4; i++) {
        int idx = tid + i * 256;
        int r = idx >> 3, c16 = idx & 7;
        uint32_t sw = r * 128 + ((c16 ^ (r & 7)) * 16);
        size_t g = qkb + (size_t)(q0 + r) * HDIM + c16 * 8;
        CPA(smb + sw,         q_hi + g);
        CPA(smb + 16384 + sw, q_lo + g);
    }

    auto load_kv = [&](int s, int c) {
        uint32_t sb = smb + 32768 + s * 32768;
        int kv0 = c * 64;
        #pragma unroll
        for (int i = 0; i < 2; i++) {
            int idx = tid + i * 256;
            int r = idx >> 3, c16 = idx & 7;
            uint32_t sw = r * 128 + ((c16 ^ (r & 7)) * 16);
            size_t gk = qkb + (size_t)(kv0 + r) * HDIM + c16 * 8;
            size_t gv = vtb + (size_t)r * SEQ + kv0 + c16 * 8;
            CPA(sb + sw,          k_hi + gk);
            CPA(sb + 8192 + sw,   k_lo + gk);
            CPA(sb + 16384 + sw,  vt_hi + gv);
            CPA(sb + 24576 + sw,  vt_lo + gv);
        }
    };

    load_kv(0, 0);
    CPC();                      // group G0 = Q + chunk0

    const int cmax = 2 * qt + 1;
    const int wrow = q0 + 16 * w;              // warp's first q row
    const int cmax_w = (wrow + 15) >> 6;       // last chunk this warp needs
    const int fr = lane & 15;
    const int fc = lane >> 4;
    const int rg = lane >> 2;                  // row within m8
    const int cg = (lane & 3) * 2;             // col pair base

    float mrow[2] = {-INFINITY, -INFINITY};
    float lrow[2] = {0.f, 0.f};
    float o[8][4];
    #pragma unroll
    for (int dt = 0; dt < 8; dt++)
        #pragma unroll
        for (int q = 0; q < 4; q++) o[dt][q] = 0.f;

    for (int c = 0; c <= cmax; c++) {
        const int s = c & 1;
        if (c < cmax) { load_kv(s ^ 1, c + 1); CPC(); CPW1(); }
        else          { CPW0(); }
        __syncthreads();

        if (c <= cmax_w) {
            const uint32_t kb = smb + 32768 + s * 32768;
            float sacc[8][4];
            #pragma unroll
            for (int nt = 0; nt < 8; nt++)
                #pragma unroll
                for (int q = 0; q < 4; q++) sacc[nt][q] = 0.f;

            // S = Q K^T (3-term)
            #pragma unroll
            for (int j = 0; j < 4; j++) {
                uint32_t ah[4], al[4];
                int rr = 16 * w + fr;
                int cq = j * 2 + fc;
                uint32_t qo = rr * 128 + ((cq ^ (rr & 7)) * 16);
                LDSM4(ah, smb + qo);
                LDSM4(al, smb + 16384 + qo);
                #pragma unroll
                for (int g = 0; g < 4; g++) {
                    uint32_t kh4[4], kl4[4];
                    int kr = 16 * g + fr;
                    uint32_t ko = kr * 128 + ((cq ^ (kr & 7)) * 16);
                    LDSM4(kh4, kb + ko);
                    LDSM4(kl4, kb + 8192 + ko);
                    MMA16816(sacc[2*g],   ah, kh4[0], kh4[2]);
                    MMA16816(sacc[2*g+1], ah, kh4[1], kh4[3]);
                    MMA16816(sacc[2*g],   ah, kl4[0], kl4[2]);
                    MMA16816(sacc[2*g+1], ah, kl4[1], kl4[3]);
                    MMA16816(sacc[2*g],   al, kh4[0], kh4[2]);
                    MMA16816(sacc[2*g+1], al, kh4[1], kh4[3]);
                }
            }

            // causal mask (only diagonal-straddling chunks)
            const int kv0 = c * 64;
            if (kv0 + 63 > wrow) {
                int r0g = wrow + rg;
                #pragma unroll
                for (int nt = 0; nt < 8; nt++) {
                    int col = kv0 + nt * 8 + cg;
                    if (col     > r0g)     sacc[nt][0] = -INFINITY;
                    if (col + 1 > r0g)     sacc[nt][1] = -INFINITY;
                    if (col     > r0g + 8) sacc[nt][2] = -INFINITY;
                    if (col + 1 > r0g + 8) sacc[nt][3] = -INFINITY;
                }
            }

            // online softmax (rows spread over 4 lanes sharing lane>>2)
            float mc0 = -INFINITY, mc1 = -INFINITY;
            #pragma unroll
            for (int nt = 0; nt < 8; nt++) {
                mc0 = fmaxf(mc0, fmaxf(sacc[nt][0], sacc[nt][1]));
                mc1 = fmaxf(mc1, fmaxf(sacc[nt][2], sacc[nt][3]));
            }
            mc0 = fmaxf(mc0, __shfl_xor_sync(0xffffffffu, mc0, 1));
            mc0 = fmaxf(mc0, __shfl_xor_sync(0xffffffffu, mc0, 2));
            mc1 = fmaxf(mc1, __shfl_xor_sync(0xffffffffu, mc1, 1));
            mc1 = fmaxf(mc1, __shfl_xor_sync(0xffffffffu, mc1, 2));
            float mn0 = fmaxf(mrow[0], mc0), mn1 = fmaxf(mrow[1], mc1);
            float a0 = __expf((mrow[0] - mn0) * SOFT_SCALE);
            float a1 = __expf((mrow[1] - mn1) * SOFT_SCALE);
            float rs0 = 0.f, rs1 = 0.f;
            #pragma unroll
            for (int nt = 0; nt < 8; nt++) {
                sacc[nt][0] = __expf((sacc[nt][0] - mn0) * SOFT_SCALE);
                sacc[nt][1] = __expf((sacc[nt][1] - mn0) * SOFT_SCALE);
                sacc[nt][2] = __expf((sacc[nt][2] - mn1) * SOFT_SCALE);
                sacc[nt][3] = __expf((sacc[nt][3] - mn1) * SOFT_SCALE);
                rs0 += sacc[nt][0] + sacc[nt][1];
                rs1 += sacc[nt][2] + sacc[nt][3];
            }
            rs0 += __shfl_xor_sync(0xffffffffu, rs0, 1);
            rs0 += __shfl_xor_sync(0xffffffffu, rs0, 2);
            rs1 += __shfl_xor_sync(0xffffffffu, rs1, 1);
            rs1 += __shfl_xor_sync(0xffffffffu, rs1, 2);
            lrow[0] = lrow[0] * a0 + rs0;
            lrow[1] = lrow[1] * a1 + rs1;
            mrow[0] = mn0; mrow[1] = mn1;
            #pragma unroll
            for (int dt = 0; dt < 8; dt++) {
                o[dt][0] *= a0; o[dt][1] *= a0;
                o[dt][2] *= a1; o[dt][3] *= a1;
            }

            // O += P V  (P built register-to-register as A-fragments)
            const uint32_t vb = kb + 16384;
            #pragma unroll
            for (int j = 0; j < 4; j++) {
                uint32_t ph[4], pl[4];
                ph[0] = pk_hi(sacc[2*j][0],   sacc[2*j][1]);
                ph[1] = pk_hi(sacc[2*j][2],   sacc[2*j][3]);
                ph[2] = pk_hi(sacc[2*j+1][0], sacc[2*j+1][1]);
                ph[3] = pk_hi(sacc[2*j+1][2], sacc[2*j+1][3]);
                pl[0] = pk_lo(sacc[2*j][0],   sacc[2*j][1],   ph[0]);
                pl[1] = pk_lo(sacc[2*j][2],   sacc[2*j][3],   ph[1]);
                pl[2] = pk_lo(sacc[2*j+1][0], sacc[2*j+1][1], ph[2]);
                pl[3] = pk_lo(sacc[2*j+1][2], sacc[2*j+1][3], ph[3]);
                int cv = j * 2 + fc;
                #pragma unroll
                for (int g = 0; g < 4; g++) {
                    uint32_t vh4[4], vl4[4];
                    int vr = 16 * g + fr;
                    uint32_t vo = vr * 128 + ((cv ^ (vr & 7)) * 16);
                    LDSM4(vh4, vb + vo);
                    LDSM4(vl4, vb + 8192 + vo);
                    MMA16816(o[2*g],   ph, vh4[0], vh4[2]);
                    MMA16816(o[2*g+1], ph, vh4[1], vh4[3]);
                    MMA16816(o[2*g],   ph, vl4[0], vl4[2]);
                    MMA16816(o[2*g+1], ph, vl4[1], vl4[3]);
                    MMA16816(o[2*g],   pl, vh4[0], vh4[2]);
                    MMA16816(o[2*g+1], pl, vh4[1], vh4[3]);
                }
            }
        }
        __syncthreads();
    }

    // epilogue: normalize, split to bf16 hi/lo for proj GEMM
    const float inv0 = 1.0f / lrow[0];
    const float inv1 = 1.0f / lrow[1];
    const int b = bh >> 4;
    const int hh = bh & 15;
    const int r = wrow + rg;
    #pragma unroll
    for (int dt = 0; dt < 8; dt++) {
        int d = dt * 8 + cg;
        size_t i0 = ((size_t)(b * SEQ + r)) * CDIM + hh * HDIM + d;
        size_t i1 = i0 + 8 * CDIM;
        uint32_t h0 = pk_hi(o[dt][0] * inv0, o[dt][1] * inv0);
        uint32_t l0 = pk_lo(o[dt][0] * inv0, o[dt][1] * inv0, h0);
        uint32_t h1 = pk_hi(o[dt][2] * inv1, o[dt][3] * inv1);
        uint32_t l1 = pk_lo(o[dt][2] * inv1, o[dt][3] * inv1, h1);
        *(uint32_t*)(at_hi + i0) = h0;
        *(uint32_t*)(at_lo + i0) = l0;
        *(uint32_t*)(at_hi + i1) = h1;
        *(uint32_t*)(at_lo + i1) = l1;
    }
}

// ---------------------------------------------------------------------------
// Launch: inputs x, Wk, Wq, Wv, Wp, bp
// ---------------------------------------------------------------------------
extern "C" void kernel_launch(void* const* d_in, const int* in_sizes, int n_in,
                              void* d_out, int out_size) {
    (void)in_sizes; (void)n_in; (void)out_size;
    const float* x  = (const float*)d_in[0];
    const float* Wk = (const float*)d_in[1];
    const float* Wq = (const float*)d_in[2];
    const float* Wv = (const float*)d_in[3];
    const float* Wp = (const float*)d_in[4];
    const float* bp = (const float*)d_in[5];
    float* out = (float*)d_out;

    cudaFuncSetAttribute((const void*)mm_kernel,
                         cudaFuncAttributeMaxDynamicSharedMemorySize, MM_SMEM);
    cudaFuncSetAttribute((const void*)flash_kernel,
                         cudaFuncAttributeMaxDynamicSharedMemorySize, FL_SMEM);

    __nv_bfloat16 *xh, *xl;
    cudaGetSymbolAddress((void**)&xh, xs_hi);
    cudaGetSymbolAddress((void**)&xl, xs_lo);

    split_kernel<<<(BT * CDIM) / (256 * 8), 256>>>(x, xh, xl);
    wt_kernel<<<dim3(32, 32, 4), 256>>>(Wq, Wk, Wv, Wp);
    mm_kernel<<<dim3(CDIM / 128, BT / 128, 3), 256, MM_SMEM>>>(0, nullptr, nullptr);
    flash_kernel<<<dim3(SEQ / 128, NBH), 256, FL_SMEM>>>();
    mm_kernel<<<dim3(CDIM / 128, BT / 128, 1), 256, MM_SMEM>>>(1, bp, out);
}